// round 15
// baseline (speedup 1.0000x reference)
#include <cuda_runtime.h>

#define DD 8

typedef unsigned long long u64;

// constant layout (all pre-scaled by sigma0 where marked):
// [0..63]   w      : dup(-0.5*log2e/L[a][k]^2)
// [64..191] ks     : per j: 8x dup(-s0*KMm[c][j]), 8x dup(+s0*Km[c][j])
// [192..223] pl    : per j: (dup(-lj2_j), dup(s0*alpha_j), dup(s0*beta_j), dup(s0*gamma_j))
#define C_W   0
#define C_KS  64
#define C_PL  192
#define C_TOT 224

__constant__ __align__(16) u64 cC[C_TOT];

// packed f32x2 ops (Blackwell sm_103a)
#define FMA2(d,a,b,c) asm("fma.rn.f32x2 %0, %1, %2, %3;" : "=l"(d) : "l"(a), "l"(b), "l"(c))
#define MUL2(d,a,b)   asm("mul.rn.f32x2 %0, %1, %2;"     : "=l"(d) : "l"(a), "l"(b))
#define ADD2(d,a,b)   asm("add.rn.f32x2 %0, %1, %2;"     : "=l"(d) : "l"(a), "l"(b))

__device__ __forceinline__ u64 pack2(float lo, float hi) {
    u64 r; asm("mov.b64 %0, {%1, %2};" : "=l"(r) : "f"(lo), "f"(hi)); return r;
}
__device__ __forceinline__ void unpack2(u64 v, float& lo, float& hi) {
    asm("mov.b64 {%0, %1}, %2;" : "=f"(lo), "=f"(hi) : "l"(v));
}
__device__ __forceinline__ float ex2a(float x) {
    float r; asm("ex2.approx.f32 %0, %1;" : "=f"(r) : "f"(x)); return r;
}
__device__ __forceinline__ u64 dup(float v) {
    unsigned u = __float_as_uint(v);
    return ((u64)u << 32) | (u64)u;
}

// ---------- setup kernel: derive constants, write DIRECTLY into cC's backing store ----------
__global__ void setup_kernel(const float* __restrict__ L, const float* __restrict__ sig,
                             u64* __restrict__ cc)
{
    asm volatile("griddepcontrol.launch_dependents;");

    int tid = threadIdx.x;            // 0..63
    int c = tid >> 3, j = tid & 7;
    float s0 = sig[0];
    float Ljc = L[j * DD + c];
    float inv2_jc = 1.0f / (Ljc * Ljc);
    float L0c = L[c];
    float inv2_0c = 1.0f / (L0c * L0c);
    float Mcj = inv2_0c + inv2_jc;
    float L0j = L[j];
    float lj2 = L0j * L0j;
    float Kcj = sig[j] / (lj2 * lj2) * Mcj * Mcj;
    cc[C_KS + j * 16 + c]     = dup(-s0 * Kcj / Mcj);   // A = -s0*KMm
    cc[C_KS + j * 16 + 8 + c] = dup( s0 * Kcj);         // B = +s0*Km
    float Lak = L[c * DD + j];
    cc[C_W + c * DD + j] = dup(-0.5f * 1.44269504088896340736f / (Lak * Lak));
    if (c == j) {
        int l = c;
        float tl = Mcj;                       // M[l][l]
        float c1 = 5.0f * tl + lj2 * tl * tl;
        float c2 = tl * tl;
        float c3 = 2.0f + lj2 * tl;
        float F  = sig[l] / (lj2 * lj2);
        float Kd = Kcj;
        float Md = 1.0f / tl;
        cc[C_PL + l * 4 + 0] = dup(-lj2);                           // -lj2 (unscaled)
        cc[C_PL + l * 4 + 1] = dup(s0 * (F * c3 - Kd * Md * lj2));  // s0*alpha
        cc[C_PL + l * 4 + 2] = dup(s0 * (-F * c1 + Kd * (Md + lj2))); // s0*beta
        cc[C_PL + l * 4 + 3] = dup(s0 * (F * c2 - Kd));             // s0*gamma
    }
}

// ---------- main kernel ----------
// out[n,m] = E0 * S   (sigma0 folded into constants)
//   d_k = (x1[n,k]-x2[m,k])^2 ; E_a = exp2( sum_k d_k * w[a,k] ) ; Q_k = d_k*E_k
//   acc'_j = sum_c A[c,j]*E_c + sum_c B[c,j]*Q_c          (= -s0*acc_j)
//   z'_j   = (-lj2_j)*E_j + Q_j                            (= -E_j*(lj2_j-d_j))
//   S += acc'_j*z'_j + E_j*(alpha~*E_j + beta~*Q_j) + gamma~*Q_j^2
//
// Block tile: 8 n-rows x 128 m-cols. 128 threads (32x4).
// 4 packed pairs/thread, explicitly interleaved. Almost every S-loop FMA2 has a
// cbank multiplier -> <=2 distinct RF operand banks -> rt=2 (RF-banking aware).

__global__ __launch_bounds__(128, 3) void taylor_rbf_kernel(
    const float* __restrict__ x1, const float* __restrict__ x2,
    float* __restrict__ out, int N, int M)
{
    __shared__ __align__(16) u64 x1d[8 * DD];    // dup(x1[n0+r][k]), r=0..7
    __shared__ __align__(16) u64 nx2[DD * 64];   // (-x2[m0+2p][k], -x2[m0+2p+1][k]), p=0..63

    const int tx = threadIdx.x;          // 0..31
    const int ty = threadIdx.y;          // 0..3
    const int tid = ty * 32 + tx;        // 0..127

    // ---- stage x tiles (no cC access here) ----
    const int n0 = blockIdx.y * 8, m0 = blockIdx.x * 128;
#pragma unroll
    for (int i = 0; i < 4; i++) {        // nx2: 512 entries, 4 per thread
        int idx = tid + 128 * i;
        int k = idx >> 6, p = idx & 63;
        int mm = m0 + 2 * p;
        float a = (mm     < M) ? x2[mm * DD + k]       : 0.0f;
        float b = (mm + 1 < M) ? x2[(mm + 1) * DD + k] : 0.0f;
        nx2[k * 64 + p] = pack2(-a, -b);
    }
    if (tid < 64) {                      // x1d: 64 entries
        int r = tid >> 3, k = tid & 7;
        int nn = n0 + r;
        x1d[r * DD + k] = dup((nn < N) ? x1[nn * DD + k] : 0.0f);
    }
    __syncthreads();

    // ---- d for 4 pairs (p>>1 selects row, p&1 selects m-pair col) ----
    u64 d[4][DD], E[4][DD];
#pragma unroll
    for (int k = 0; k < DD; k++) {
        u64 xv0 = nx2[k * 64 + tx];
        u64 xv1 = nx2[k * 64 + tx + 32];
        u64 xr0 = x1d[ty * DD + k];
        u64 xr1 = x1d[(ty + 4) * DD + k];
        u64 f0, f1, f2, f3;
        ADD2(f0, xr0, xv0);
        ADD2(f1, xr0, xv1);
        ADD2(f2, xr1, xv0);
        ADD2(f3, xr1, xv1);
        MUL2(d[0][k], f0, f0);
        MUL2(d[1][k], f1, f1);
        MUL2(d[2][k], f2, f2);
        MUL2(d[3][k], f3, f3);
    }

    // ---- PDL sync: setup kernel's constant writes must be visible below ----
    asm volatile("griddepcontrol.wait;" ::: "memory");

    // ---- E_a = exp2( d . w_a ): 4 pair-chains interleaved per k-step ----
#pragma unroll
    for (int a = 0; a < DD; a++) {
        const u64* wr = &cC[C_W + a * DD];
        u64 s[4];
#pragma unroll
        for (int p = 0; p < 4; p++) MUL2(s[p], d[p][0], wr[0]);
#pragma unroll
        for (int k = 1; k < DD; k++) {
#pragma unroll
            for (int p = 0; p < 4; p++) FMA2(s[p], d[p][k], wr[k], s[p]);
        }
#pragma unroll
        for (int p = 0; p < 4; p++) {
            float lo, hi;
            unpack2(s[p], lo, hi);
            E[p][a] = pack2(ex2a(lo), ex2a(hi));
        }
    }

    // ---- convert d -> Q = d*E in place (S-loop uses only E and Q) ----
#pragma unroll
    for (int k = 0; k < DD; k++)
#pragma unroll
        for (int p = 0; p < 4; p++) MUL2(d[p][k], d[p][k], E[p][k]);
    // from here on, d[p][k] holds Q_k

    // ---- S-loop over j; 4 pairs interleaved; cbank-multiplier FMA2s (rt2) ----
    u64 S[4];
    S[0] = S[1] = S[2] = S[3] = dup(0.0f);
#pragma unroll
    for (int j = 0; j < DD; j++) {
        const u64* kA = &cC[C_KS + j * 16];        // 8x (-s0*KMm)
        const u64* kB = &cC[C_KS + j * 16 + 8];    // 8x (+s0*Km)
        const u64* pl = &cC[C_PL + j * 4];         // -lj2, a~, b~, g~

        u64 acc[4];
#pragma unroll
        for (int p = 0; p < 4; p++) MUL2(acc[p], kA[0], E[p][0]);
#pragma unroll
        for (int c = 1; c < DD; c++) {
#pragma unroll
            for (int p = 0; p < 4; p++) FMA2(acc[p], kA[c], E[p][c], acc[p]);
        }
#pragma unroll
        for (int c = 0; c < DD; c++) {
#pragma unroll
            for (int p = 0; p < 4; p++) FMA2(acc[p], kB[c], d[p][c], acc[p]);
        }

        // tail: z' = (-lj2)*E_j + Q_j ; u = a~*E_j + b~*Q_j ; t4 = g~*Q_j
        u64 z[4], u_[4], t4[4];
#pragma unroll
        for (int p = 0; p < 4; p++) FMA2(z[p], pl[0], E[p][j], d[p][j]);
#pragma unroll
        for (int p = 0; p < 4; p++) MUL2(u_[p], pl[2], d[p][j]);
#pragma unroll
        for (int p = 0; p < 4; p++) FMA2(u_[p], pl[1], E[p][j], u_[p]);
#pragma unroll
        for (int p = 0; p < 4; p++) MUL2(t4[p], pl[3], d[p][j]);
#pragma unroll
        for (int p = 0; p < 4; p++) FMA2(S[p], acc[p], z[p], S[p]);
#pragma unroll
        for (int p = 0; p < 4; p++) FMA2(S[p], E[p][j], u_[p], S[p]);
#pragma unroll
        for (int p = 0; p < 4; p++) FMA2(S[p], d[p][j], t4[p], S[p]);
    }

    // ---- outputs: res = E0 * S (sigma0 already folded into constants) ----
#pragma unroll
    for (int p = 0; p < 4; p++) {
        int n = n0 + ty + 4 * (p >> 1);
        int m = m0 + 2 * (tx + 32 * (p & 1));
        if (n >= N || m >= M) continue;
        u64 res; MUL2(res, S[p], E[p][0]);
        long idx = (long)n * M + m;
        if (m + 1 < M) {
            *reinterpret_cast<u64*>(&out[idx]) = res;
        } else {
            float lo, hi; unpack2(res, lo, hi);
            out[idx] = lo;
        }
    }
}

extern "C" void kernel_launch(void* const* d_in, const int* in_sizes, int n_in,
                              void* d_out, int out_size)
{
    const float* x1  = (const float*)d_in[0];
    const float* x2  = (const float*)d_in[1];
    const float* L   = (const float*)d_in[2];
    const float* sig = (const float*)d_in[3];
    float* out = (float*)d_out;

    int N = in_sizes[0] / DD;
    int M = in_sizes[1] / DD;

    void* cc_addr = nullptr;
    cudaGetSymbolAddress(&cc_addr, cC);
    setup_kernel<<<1, 64>>>(L, sig, (u64*)cc_addr);

    // Main kernel with Programmatic Dependent Launch
    dim3 block(32, 4);                                     // 128 threads
    dim3 grid((M + 127) / 128, (N + 7) / 8);

    cudaLaunchConfig_t cfg = {};
    cfg.gridDim = grid;
    cfg.blockDim = block;
    cfg.dynamicSmemBytes = 0;
    cfg.stream = 0;
    cudaLaunchAttribute attrs[1];
    attrs[0].id = cudaLaunchAttributeProgrammaticStreamSerialization;
    attrs[0].val.programmaticStreamSerializationAllowed = 1;
    cfg.attrs = attrs;
    cfg.numAttrs = 1;

    cudaLaunchKernelEx(&cfg, taylor_rbf_kernel, x1, x2, out, N, M);
}

// round 17
// speedup vs baseline: 1.1817x; 1.1817x over previous
#include <cuda_runtime.h>
#include <cstdint>

#define DD 8

typedef unsigned long long u64;
typedef unsigned int u32;

// cbank: only the exp weights + sig0
#define C_W   0
#define C_S0  64
#define C_TOT 72
__constant__ __align__(16) u64 cC[C_TOT];

// global scratch for S-loop constants: [0..127] ks (per j: 8x KMm, 8x -Km) | [128..159] pl (lj2,alpha,beta,gamma)
#define G_KS  0
#define G_PL  128
#define G_TOT 160
__device__ __align__(16) u64 gScratch[G_TOT];

// packed f32x2 ops (Blackwell sm_103a)
#define FMA2(d,a,b,c) asm("fma.rn.f32x2 %0, %1, %2, %3;" : "=l"(d) : "l"(a), "l"(b), "l"(c))
#define MUL2(d,a,b)   asm("mul.rn.f32x2 %0, %1, %2;"     : "=l"(d) : "l"(a), "l"(b))
#define ADD2(d,a,b)   asm("add.rn.f32x2 %0, %1, %2;"     : "=l"(d) : "l"(a), "l"(b))

__device__ __forceinline__ u64 pack2(float lo, float hi) {
    u64 r; asm("mov.b64 %0, {%1, %2};" : "=l"(r) : "f"(lo), "f"(hi)); return r;
}
__device__ __forceinline__ void unpack2(u64 v, float& lo, float& hi) {
    asm("mov.b64 {%0, %1}, %2;" : "=f"(lo), "=f"(hi) : "l"(v));
}
__device__ __forceinline__ float ex2a(float x) {
    float r; asm("ex2.approx.f32 %0, %1;" : "=f"(r) : "f"(x)); return r;
}
__device__ __forceinline__ u64 dup(float v) {
    unsigned u = __float_as_uint(v);
    return ((u64)u << 32) | (u64)u;
}
__device__ __forceinline__ u32 smem_u32(const void* p) {
    u32 a;
    asm("{ .reg .u64 t; cvta.to.shared.u64 t, %1; cvt.u32.u64 %0, t; }" : "=r"(a) : "l"(p));
    return a;
}
// forced scalar 64-bit shared load (avoid ptxas LDS.128 vectorization / 4-reg temps)
__device__ __forceinline__ u64 lds64(u32 addr) {
    u64 r; asm("ld.shared.b64 %0, [%1];" : "=l"(r) : "r"(addr)); return r;
}

// ---------- setup kernel ----------
__global__ void setup_kernel(const float* __restrict__ L, const float* __restrict__ sig,
                             u64* __restrict__ cw, u64* __restrict__ gs)
{
    asm volatile("griddepcontrol.launch_dependents;");

    int tid = threadIdx.x;            // 0..63
    int c = tid >> 3, j = tid & 7;
    float Ljc = L[j * DD + c];
    float inv2_jc = 1.0f / (Ljc * Ljc);
    float L0c = L[c];
    float inv2_0c = 1.0f / (L0c * L0c);
    float Mcj = inv2_0c + inv2_jc;
    float L0j = L[j];
    float lj2 = L0j * L0j;
    float Kcj = sig[j] / (lj2 * lj2) * Mcj * Mcj;
    gs[G_KS + j * 16 + c]     = dup(Kcj / Mcj);    // KMm
    gs[G_KS + j * 16 + 8 + c] = dup(-Kcj);         // -Km
    float Lak = L[c * DD + j];
    cw[C_W + c * DD + j] = dup(-0.5f * 1.44269504088896340736f / (Lak * Lak));
    if (c == j) {
        int l = c;
        float tl = Mcj;                       // M[l][l]
        float c1 = 5.0f * tl + lj2 * tl * tl;
        float c2 = tl * tl;
        float c3 = 2.0f + lj2 * tl;
        float F  = sig[l] / (lj2 * lj2);
        float Kd = Kcj;
        float Md = 1.0f / tl;
        gs[G_PL + l * 4 + 0] = dup(lj2);
        gs[G_PL + l * 4 + 1] = dup(F * c3 - Kd * Md * lj2);      // alpha
        gs[G_PL + l * 4 + 2] = dup(-F * c1 + Kd * (Md + lj2));   // beta
        gs[G_PL + l * 4 + 3] = dup(F * c2 - Kd);                 // gamma
    }
    if (tid == 0) cw[C_S0] = dup(sig[0]);
}

// ---------- main kernel (math identical to R14 best) ----------
// out[n,m] = sigma0 * E0 * S_total
//   d_k = (x1[n,k]-x2[m,k])^2 ; E_a = exp2( sum_k d_k * w[a,k] )
//   S_total = sum_j E_j * [ acc_j*(lj2_j - d_j) + (alpha + beta d + gamma d^2)_j * E_j ]
//   acc_j = sum_c (KMm[c,j] - Km[c,j] d_c) E_c
// w from cbank (64 LDC); ks/pl from SMEM via scalar LDS.64 (floor 2 vs LDC 8/word).

__global__ __launch_bounds__(128, 3) void taylor_rbf_kernel(
    const float* __restrict__ x1, const float* __restrict__ x2,
    float* __restrict__ out, int N, int M)
{
    __shared__ __align__(16) u64 x1d[8 * DD];    // dup(x1[n0+r][k])
    __shared__ __align__(16) u64 nx2[DD * 64];   // (-x2[m0+2p][k], -x2[m0+2p+1][k])
    __shared__ __align__(16) u64 ksD[DD * 16];   // per j: 8x KMm, 8x -Km
    __shared__ __align__(16) u64 plD[DD * 4];    // per j: lj2, alpha, beta, gamma

    const int tx = threadIdx.x;          // 0..31
    const int ty = threadIdx.y;          // 0..3
    const int tid = ty * 32 + tx;        // 0..127

    // ---- stage x tiles (overlaps setup kernel under PDL) ----
    const int n0 = blockIdx.y * 8, m0 = blockIdx.x * 128;
#pragma unroll
    for (int i = 0; i < 4; i++) {        // nx2: 512 entries, 4 per thread
        int idx = tid + 128 * i;
        int k = idx >> 6, p = idx & 63;
        int mm = m0 + 2 * p;
        float a = (mm     < M) ? x2[mm * DD + k]       : 0.0f;
        float b = (mm + 1 < M) ? x2[(mm + 1) * DD + k] : 0.0f;
        nx2[k * 64 + p] = pack2(-a, -b);
    }
    if (tid < 64) {                      // x1d: 64 entries
        int r = tid >> 3, k = tid & 7;
        int nn = n0 + r;
        x1d[r * DD + k] = dup((nn < N) ? x1[nn * DD + k] : 0.0f);
    }

    // ---- PDL sync, then stage S-loop constants global -> smem ----
    asm volatile("griddepcontrol.wait;" ::: "memory");
    ksD[tid] = gScratch[G_KS + tid];               // 128 entries
    if (tid < 32) plD[tid] = gScratch[G_PL + tid]; // 32 entries
    __syncthreads();

    const u64 negone = dup(-1.0f);
    const u32 ks_base = smem_u32(ksD);
    const u32 pl_base = smem_u32(plD);

    // ---- d for 4 pairs (p>>1 selects row, p&1 selects m-pair col) ----
    u64 d[4][DD], E[4][DD];
#pragma unroll
    for (int k = 0; k < DD; k++) {
        u64 xv0 = nx2[k * 64 + tx];
        u64 xv1 = nx2[k * 64 + tx + 32];
        u64 xr0 = x1d[ty * DD + k];
        u64 xr1 = x1d[(ty + 4) * DD + k];
        u64 f0, f1, f2, f3;
        ADD2(f0, xr0, xv0);
        ADD2(f1, xr0, xv1);
        ADD2(f2, xr1, xv0);
        ADD2(f3, xr1, xv1);
        MUL2(d[0][k], f0, f0);
        MUL2(d[1][k], f1, f1);
        MUL2(d[2][k], f2, f2);
        MUL2(d[3][k], f3, f3);
    }

    // ---- E_a = exp2( d . w_a ): weights via cbank, 4 pair-chains interleaved ----
#pragma unroll
    for (int a = 0; a < DD; a++) {
        const u64* wr = &cC[C_W + a * DD];
        u64 s[4];
#pragma unroll
        for (int p = 0; p < 4; p++) MUL2(s[p], d[p][0], wr[0]);
#pragma unroll
        for (int k = 1; k < DD; k++) {
#pragma unroll
            for (int p = 0; p < 4; p++) FMA2(s[p], d[p][k], wr[k], s[p]);
        }
#pragma unroll
        for (int p = 0; p < 4; p++) {
            float lo, hi;
            unpack2(s[p], lo, hi);
            E[p][a] = pack2(ex2a(lo), ex2a(hi));
        }
    }

    // ---- merged S + corr loop over j; consts via scalar LDS.64, shared by 4 pairs ----
    u64 S[4];
    S[0] = S[1] = S[2] = S[3] = dup(0.0f);
#pragma unroll
    for (int j = 0; j < DD; j++) {
        const u32 kj = ks_base + j * 128;    // 16 u64 per j
        const u32 pj = pl_base + j * 32;     // 4 u64 per j

        u64 acc[4], acc2[4], wp[4];
        // c = 0 -> acc, c = 1 -> acc2
        {
            u64 km = lds64(kj + 0 * 8), nk = lds64(kj + 64 + 0 * 8);
#pragma unroll
            for (int p = 0; p < 4; p++) FMA2(wp[p], nk, d[p][0], km);
#pragma unroll
            for (int p = 0; p < 4; p++) MUL2(acc[p], wp[p], E[p][0]);
        }
        {
            u64 km = lds64(kj + 1 * 8), nk = lds64(kj + 64 + 1 * 8);
#pragma unroll
            for (int p = 0; p < 4; p++) FMA2(wp[p], nk, d[p][1], km);
#pragma unroll
            for (int p = 0; p < 4; p++) MUL2(acc2[p], wp[p], E[p][1]);
        }
#pragma unroll
        for (int c = 2; c < DD; c += 2) {
            u64 km0 = lds64(kj + c * 8), nk0 = lds64(kj + 64 + c * 8);
#pragma unroll
            for (int p = 0; p < 4; p++) FMA2(wp[p], nk0, d[p][c], km0);
#pragma unroll
            for (int p = 0; p < 4; p++) FMA2(acc[p], wp[p], E[p][c], acc[p]);
            u64 km1 = lds64(kj + (c + 1) * 8), nk1 = lds64(kj + 64 + (c + 1) * 8);
#pragma unroll
            for (int p = 0; p < 4; p++) FMA2(wp[p], nk1, d[p][c + 1], km1);
#pragma unroll
            for (int p = 0; p < 4; p++) FMA2(acc2[p], wp[p], E[p][c + 1], acc2[p]);
        }
#pragma unroll
        for (int p = 0; p < 4; p++) ADD2(acc[p], acc[p], acc2[p]);

        // tail: S += E_j * ( acc*(lj2-d_j) + (alpha + beta d + gamma d^2) * E_j )
        u64 plj = lds64(pj + 0);       // lj2
        u64 pla = lds64(pj + 8);       // alpha
        u64 plb = lds64(pj + 16);      // beta
        u64 plg = lds64(pj + 24);      // gamma
        u64 t[4], g[4], py[4], v[4];
#pragma unroll
        for (int p = 0; p < 4; p++) FMA2(t[p], d[p][j], negone, plj);
#pragma unroll
        for (int p = 0; p < 4; p++) FMA2(g[p], plg, d[p][j], plb);
#pragma unroll
        for (int p = 0; p < 4; p++) FMA2(py[p], d[p][j], g[p], pla);
#pragma unroll
        for (int p = 0; p < 4; p++) MUL2(v[p], acc[p], t[p]);
#pragma unroll
        for (int p = 0; p < 4; p++) FMA2(v[p], py[p], E[p][j], v[p]);
#pragma unroll
        for (int p = 0; p < 4; p++) FMA2(S[p], E[p][j], v[p], S[p]);
    }

    // ---- outputs: res = sig0 * E0 * S ----
#pragma unroll
    for (int p = 0; p < 4; p++) {
        int n = n0 + ty + 4 * (p >> 1);
        int m = m0 + 2 * (tx + 32 * (p & 1));
        if (n >= N || m >= M) continue;
        u64 e0; MUL2(e0, E[p][0], cC[C_S0]);
        u64 res; MUL2(res, S[p], e0);
        long idx = (long)n * M + m;
        if (m + 1 < M) {
            *reinterpret_cast<u64*>(&out[idx]) = res;
        } else {
            float lo, hi; unpack2(res, lo, hi);
            out[idx] = lo;
        }
    }
}

extern "C" void kernel_launch(void* const* d_in, const int* in_sizes, int n_in,
                              void* d_out, int out_size)
{
    const float* x1  = (const float*)d_in[0];
    const float* x2  = (const float*)d_in[1];
    const float* L   = (const float*)d_in[2];
    const float* sig = (const float*)d_in[3];
    float* out = (float*)d_out;

    int N = in_sizes[0] / DD;
    int M = in_sizes[1] / DD;

    void* cw_addr = nullptr;
    void* gs_addr = nullptr;
    cudaGetSymbolAddress(&cw_addr, cC);
    cudaGetSymbolAddress(&gs_addr, gScratch);
    setup_kernel<<<1, 64>>>(L, sig, (u64*)cw_addr, (u64*)gs_addr);

    // Main kernel with Programmatic Dependent Launch
    dim3 block(32, 4);                                     // 128 threads
    dim3 grid((M + 127) / 128, (N + 7) / 8);

    cudaLaunchConfig_t cfg = {};
    cfg.gridDim = grid;
    cfg.blockDim = block;
    cfg.dynamicSmemBytes = 0;
    cfg.stream = 0;
    cudaLaunchAttribute attrs[1];
    attrs[0].id = cudaLaunchAttributeProgrammaticStreamSerialization;
    attrs[0].val.programmaticStreamSerializationAllowed = 1;
    cfg.attrs = attrs;
    cfg.numAttrs = 1;

    cudaLaunchKernelEx(&cfg, taylor_rbf_kernel, x1, x2, out, N, M);
}